// round 17
// baseline (speedup 1.0000x reference)
#include <cuda_runtime.h>
#include <cuda_bf16.h>
#include <cuda_fp16.h>
#include <math.h>
#include <stdint.h>

// Problem shape (fixed)
#define BB 4
#define NN 4096
#define EE 1024
#define DD 256
#define NEG_FILL (-3.402823466385288598e+38f)
#define PSCALE     0.0009765625f     // 2^-10: P stored scaled so f16 holds exp(S)
#define PSCALE_INV 1024.0f

// ---------------- scratch (static device globals; no allocs) ----------------
__device__ __half g_Xh  [(size_t)BB * NN * EE];
__device__ __half g_Xl  [(size_t)BB * NN * EE];
__device__ __half g_Qh  [(size_t)BB * NN * DD];
__device__ __half g_Ql  [(size_t)BB * NN * DD];
__device__ __half g_Kh  [(size_t)BB * NN * DD];
__device__ __half g_Kl  [(size_t)BB * NN * DD];
__device__ __half g_VdTh[(size_t)DD * BB * NN];  // (X@Wvd)^T  [256, B*N]
__device__ __half g_Th  [(size_t)BB * NN * DD];  // T = softmax(S)@Vd
__device__ __half g_Tl  [(size_t)BB * NN * DD];
__device__ float  g_Tp0 [(size_t)BB * NN * DD];  // T split-K partials (f32)
__device__ float  g_Tp1 [(size_t)BB * NN * DD];
__device__ float  g_rsum[(size_t)BB * NN];       // unnormalized row sums
__device__ __half g_WqTh[(size_t)DD * EE];
__device__ __half g_WqTl[(size_t)DD * EE];
__device__ __half g_WkTh[(size_t)DD * EE];
__device__ __half g_WkTl[(size_t)DD * EE];
__device__ __half g_WvdTh[(size_t)DD * EE];
__device__ __half g_WvdTl[(size_t)DD * EE];
__device__ __half g_WvuTh[(size_t)EE * DD];
__device__ __half g_WvuTl[(size_t)EE * DD];
__device__ __half g_Ph  [(size_t)BB * NN * NN];  // exp(S) * PSCALE (f16, hi only)

// ---------------- helpers ----------------
__device__ __forceinline__ uint32_t smem_u32(const void* p) {
    uint32_t a;
    asm("{ .reg .u64 t; cvta.to.shared.u64 t, %1; cvt.u32.u64 %0, t; }"
        : "=r"(a) : "l"(p));
    return a;
}
__device__ __forceinline__ void ldsm4(uint32_t* r, uint32_t a) {
    asm volatile("ldmatrix.sync.aligned.m8n8.x4.shared.b16 {%0,%1,%2,%3}, [%4];"
                 : "=r"(r[0]), "=r"(r[1]), "=r"(r[2]), "=r"(r[3]) : "r"(a));
}
// f16 x f16 -> f32 accum (main term)
__device__ __forceinline__ void mma_f16f32(float* d, const uint32_t* a, const uint32_t* b) {
    asm volatile(
        "mma.sync.aligned.m16n8k16.row.col.f32.f16.f16.f32 "
        "{%0,%1,%2,%3}, {%4,%5,%6,%7}, {%8,%9}, {%0,%1,%2,%3};"
        : "+f"(d[0]), "+f"(d[1]), "+f"(d[2]), "+f"(d[3])
        : "r"(a[0]), "r"(a[1]), "r"(a[2]), "r"(a[3]), "r"(b[0]), "r"(b[1]));
}
// f16 x f16 -> f16 accum (correction terms)
__device__ __forceinline__ void mma_f16f16(uint32_t* d, const uint32_t* a, const uint32_t* b) {
    asm volatile(
        "mma.sync.aligned.m16n8k16.row.col.f16.f16.f16.f16 "
        "{%0,%1}, {%2,%3,%4,%5}, {%6,%7}, {%0,%1};"
        : "+r"(d[0]), "+r"(d[1])
        : "r"(a[0]), "r"(a[1]), "r"(a[2]), "r"(a[3]), "r"(b[0]), "r"(b[1]));
}
__device__ __forceinline__ void cp16(uint32_t saddr, const void* gaddr) {
    asm volatile("cp.async.cg.shared.global [%0], [%1], 16;"
                 :: "r"(saddr), "l"(gaddr) : "memory");
}
#define CP_COMMIT() asm volatile("cp.async.commit_group;" ::: "memory")
#define CP_WAIT1()  asm volatile("cp.async.wait_group 1;" ::: "memory")

// swizzled offset within a Nx32-elem 16-bit tile (rows of 64B, 4x16B chunks)
__device__ __forceinline__ uint32_t tswz(int row, int chunk) {
    return (uint32_t)(row * 64 + ((chunk ^ ((row >> 1) & 3)) << 4));
}

// ===========================================================================
// f16 split-3 GEMM core: CTA tile 128x64, 4 warps (2x2) of 64x32, K-slab 32.
// ===========================================================================
#define F16_AT   8192                 // A tile 128x64B
#define F16_BT   4096                 // B tile 64x64B
#define F16_STAGE (2 * F16_AT + 2 * F16_BT)   // 24576
#define F16_SMEM (3 * F16_STAGE)              // 73728

__device__ __forceinline__ void gemm_core_f16(
    const __half* __restrict__ Ah, const __half* __restrict__ Al,
    const __half* __restrict__ Bh, const __half* __restrict__ Bl,
    int m0, int n0, int ldA, int ldB, int numIt, char* sm,
    float accF[4][4][4], uint32_t accC[4][4][2])
{
    const int tid = threadIdx.x;
    const int lane = tid & 31;
    const int wid = tid >> 5;
    const int wm = wid >> 1;
    const int wn = wid & 1;

    auto issue = [&](int stage, int it) {
        char* st = sm + stage * F16_STAGE;
        const int k0 = it << 5;
#pragma unroll
        for (int j = 0; j < 6; j++) {
            int idx = tid + j * 128;            // 0..767
            int row = idx >> 2, c = idx & 3;
            if (row < 128) {                    // A rows
                uint32_t off = tswz(row, c);
                uint32_t s0 = smem_u32(st) + off;
                cp16(s0,           Ah + (size_t)(m0 + row) * ldA + k0 + c * 8);
                cp16(s0 + F16_AT,  Al + (size_t)(m0 + row) * ldA + k0 + c * 8);
            } else {                            // B rows
                int r2 = row - 128;
                uint32_t off = tswz(r2, c);
                uint32_t s0 = smem_u32(st) + 2 * F16_AT + off;
                cp16(s0,           Bh + (size_t)(n0 + r2) * ldB + k0 + c * 8);
                cp16(s0 + F16_BT,  Bl + (size_t)(n0 + r2) * ldB + k0 + c * 8);
            }
        }
    };

    issue(0, 0); CP_COMMIT();
    if (numIt > 1) issue(1, 1);
    CP_COMMIT();

    for (int it = 0; it < numIt; ++it) {
        CP_WAIT1();
        __syncthreads();
        if (it + 2 < numIt) issue((it + 2) % 3, it + 2);
        CP_COMMIT();

        char* st = sm + (it % 3) * F16_STAGE;
        const uint32_t bAh = smem_u32(st);
        const uint32_t bAl = bAh + F16_AT;
        const uint32_t bBh = bAh + 2 * F16_AT;
        const uint32_t bBl = bBh + F16_BT;

#pragma unroll
        for (int ks = 0; ks < 2; ks++) {
            uint32_t ah[4][4], al[4][4], bh[4][2], bl[4][2];
            const int arow = wm * 64 + (lane & 15);
            const int ac = ks * 2 + (lane >> 4);
#pragma unroll
            for (int mf = 0; mf < 4; mf++) {
                uint32_t o = tswz(arow + mf * 16, ac);
                ldsm4(ah[mf], bAh + o);
                ldsm4(al[mf], bAl + o);
            }
            const int brow = wn * 32 + ((lane >> 4) & 1) * 8 + (lane & 7);
            const int bc = ks * 2 + ((lane >> 3) & 1);
#pragma unroll
            for (int nfp = 0; nfp < 2; nfp++) {
                uint32_t o = tswz(brow + nfp * 16, bc);
                uint32_t t4[4];
                ldsm4(t4, bBh + o);
                bh[2 * nfp][0] = t4[0]; bh[2 * nfp][1] = t4[1];
                bh[2 * nfp + 1][0] = t4[2]; bh[2 * nfp + 1][1] = t4[3];
                ldsm4(t4, bBl + o);
                bl[2 * nfp][0] = t4[0]; bl[2 * nfp][1] = t4[1];
                bl[2 * nfp + 1][0] = t4[2]; bl[2 * nfp + 1][1] = t4[3];
            }
#pragma unroll
            for (int mf = 0; mf < 4; mf++)
#pragma unroll
                for (int nf = 0; nf < 4; nf++) {
                    mma_f16f32(accF[mf][nf], ah[mf], bh[nf]);   // main
                    mma_f16f16(accC[mf][nf], ah[mf], bl[nf]);   // corr
                    mma_f16f16(accC[mf][nf], al[mf], bh[nf]);   // corr
                }
        }
    }
}

// final value of fragment element k (0..3) for (mf,nf)
__device__ __forceinline__ float f16v(const float* aF, const uint32_t* aC, int k) {
    __half2 c = *(const __half2*)&aC[k >> 1];
    float corr = (k & 1) ? __high2float(c) : __low2float(c);
    return aF[k] + corr;
}

// ===========================================================================
// f16 single-term core, 128x64 tile (Vd projection): occ 4.
// ===========================================================================
#define T1_AT    8192
#define T1_BT    4096
#define T1_STAGE (T1_AT + T1_BT)     // 12288
#define T1_SMEM  (3 * T1_STAGE)      // 36864

__device__ __forceinline__ void gemm_core_f16_1(
    const __half* __restrict__ Ah, const __half* __restrict__ Bh,
    int m0, int n0, int ldA, int ldB, int numIt, char* sm,
    float accF[4][4][4])
{
    const int tid = threadIdx.x;
    const int lane = tid & 31;
    const int wid = tid >> 5;
    const int wm = wid >> 1;
    const int wn = wid & 1;

    auto issue = [&](int stage, int it) {
        char* st = sm + stage * T1_STAGE;
        const int k0 = it << 5;
#pragma unroll
        for (int j = 0; j < 6; j++) {
            int idx = tid + j * 128;
            int row = idx >> 2, c = idx & 3;
            if (row < 128) {
                cp16(smem_u32(st) + tswz(row, c),
                     Ah + (size_t)(m0 + row) * ldA + k0 + c * 8);
            } else {
                int r2 = row - 128;
                cp16(smem_u32(st) + T1_AT + tswz(r2, c),
                     Bh + (size_t)(n0 + r2) * ldB + k0 + c * 8);
            }
        }
    };

    issue(0, 0); CP_COMMIT();
    if (numIt > 1) issue(1, 1);
    CP_COMMIT();

    for (int it = 0; it < numIt; ++it) {
        CP_WAIT1();
        __syncthreads();
        if (it + 2 < numIt) issue((it + 2) % 3, it + 2);
        CP_COMMIT();

        char* st = sm + (it % 3) * T1_STAGE;
        const uint32_t bAh = smem_u32(st);
        const uint32_t bBh = bAh + T1_AT;

#pragma unroll
        for (int ks = 0; ks < 2; ks++) {
            uint32_t ah[4][4], bh[4][2];
            const int arow = wm * 64 + (lane & 15);
            const int ac = ks * 2 + (lane >> 4);
#pragma unroll
            for (int mf = 0; mf < 4; mf++)
                ldsm4(ah[mf], bAh + tswz(arow + mf * 16, ac));
            const int brow = wn * 32 + ((lane >> 4) & 1) * 8 + (lane & 7);
            const int bc = ks * 2 + ((lane >> 3) & 1);
#pragma unroll
            for (int nfp = 0; nfp < 2; nfp++) {
                uint32_t t4[4];
                ldsm4(t4, bBh + tswz(brow + nfp * 16, bc));
                bh[2 * nfp][0] = t4[0]; bh[2 * nfp][1] = t4[1];
                bh[2 * nfp + 1][0] = t4[2]; bh[2 * nfp + 1][1] = t4[3];
            }
#pragma unroll
            for (int mf = 0; mf < 4; mf++)
#pragma unroll
                for (int nf = 0; nf < 4; nf++)
                    mma_f16f32(accF[mf][nf], ah[mf], bh[nf]);
        }
    }
}

// ===========================================================================
// f16 single-term core, 128x128 tile (T GEMM): 4 warps of 64x64, occ 2.
// Halves P re-reads through L2 vs the 64-wide tile (each P tile read 2x not 4x).
// ===========================================================================
#define T2_AT    8192
#define T2_BT    8192
#define T2_STAGE (T2_AT + T2_BT)     // 16384
#define T2_SMEM  (3 * T2_STAGE)      // 49152

__device__ __forceinline__ void gemm_core_f16_1w(
    const __half* __restrict__ Ah, const __half* __restrict__ Bh,
    int m0, int n0, int ldA, int ldB, int numIt, char* sm,
    float accF[4][8][4])
{
    const int tid = threadIdx.x;
    const int lane = tid & 31;
    const int wid = tid >> 5;
    const int wm = wid >> 1;
    const int wn = wid & 1;

    auto issue = [&](int stage, int it) {
        char* st = sm + stage * T2_STAGE;
        const int k0 = it << 5;
#pragma unroll
        for (int j = 0; j < 8; j++) {
            int idx = tid + j * 128;            // 0..1023
            int row = idx >> 2, c = idx & 3;
            if (row < 128) {                    // A rows
                cp16(smem_u32(st) + tswz(row, c),
                     Ah + (size_t)(m0 + row) * ldA + k0 + c * 8);
            } else {                            // B rows 0..127
                int r2 = row - 128;
                cp16(smem_u32(st) + T2_AT + tswz(r2, c),
                     Bh + (size_t)(n0 + r2) * ldB + k0 + c * 8);
            }
        }
    };

    issue(0, 0); CP_COMMIT();
    if (numIt > 1) issue(1, 1);
    CP_COMMIT();

    for (int it = 0; it < numIt; ++it) {
        CP_WAIT1();
        __syncthreads();
        if (it + 2 < numIt) issue((it + 2) % 3, it + 2);
        CP_COMMIT();

        char* st = sm + (it % 3) * T2_STAGE;
        const uint32_t bAh = smem_u32(st);
        const uint32_t bBh = bAh + T2_AT;

#pragma unroll
        for (int ks = 0; ks < 2; ks++) {
            uint32_t ah[4][4], bh[8][2];
            const int arow = wm * 64 + (lane & 15);
            const int ac = ks * 2 + (lane >> 4);
#pragma unroll
            for (int mf = 0; mf < 4; mf++)
                ldsm4(ah[mf], bAh + tswz(arow + mf * 16, ac));
            const int brow = wn * 64 + ((lane >> 4) & 1) * 8 + (lane & 7);
            const int bc = ks * 2 + ((lane >> 3) & 1);
#pragma unroll
            for (int nfp = 0; nfp < 4; nfp++) {
                uint32_t t4[4];
                ldsm4(t4, bBh + tswz(brow + nfp * 16, bc));
                bh[2 * nfp][0] = t4[0]; bh[2 * nfp][1] = t4[1];
                bh[2 * nfp + 1][0] = t4[2]; bh[2 * nfp + 1][1] = t4[3];
            }
#pragma unroll
            for (int mf = 0; mf < 4; mf++)
#pragma unroll
                for (int nf = 0; nf < 8; nf++)
                    mma_f16f32(accF[mf][nf], ah[mf], bh[nf]);
        }
    }
}

// ===========================================================================
// Kernels
// ===========================================================================

// Merged Q/K projection (split-3 core). z=0:Q z=1:K (both f16 hi/lo out)
__global__ void __launch_bounds__(128, 3)
mma_gemm_qk(const __half* __restrict__ Xh, const __half* __restrict__ Xl,
            const __half* __restrict__ Bqh, const __half* __restrict__ Bql,
            const __half* __restrict__ Bkh, const __half* __restrict__ Bkl,
            __half* __restrict__ Qh, __half* __restrict__ Ql,
            __half* __restrict__ Kh, __half* __restrict__ Kl)
{
    const int m0 = blockIdx.y * 128;
    const int n0 = blockIdx.x * 64;
    const int z = blockIdx.z;

    const __half* Bh = (z == 0) ? Bqh : Bkh;
    const __half* Bl = (z == 0) ? Bql : Bkl;

    extern __shared__ char sm[];
    float accF[4][4][4] = {};
    uint32_t accC[4][4][2] = {};
    gemm_core_f16(Xh, Xl, Bh, Bl, m0, n0, EE, EE, EE >> 5, sm, accF, accC);

    const int lane = threadIdx.x & 31;
    const int wid = threadIdx.x >> 5;
    const int wm = wid >> 1, wn = wid & 1;
    const int g = lane >> 2, t2 = (lane & 3) * 2;
    __half* Ch = (z == 0) ? Qh : Kh;
    __half* Cl = (z == 0) ? Ql : Kl;
#pragma unroll
    for (int mf = 0; mf < 4; mf++)
#pragma unroll
        for (int nf = 0; nf < 4; nf++) {
            const int r0 = m0 + wm * 64 + mf * 16 + g;
            const int c0 = n0 + wn * 32 + nf * 8 + t2;
#pragma unroll
            for (int h = 0; h < 2; h++) {
                const int r = r0 + h * 8;
                float v0 = f16v(accF[mf][nf], accC[mf][nf], h * 2 + 0);
                float v1 = f16v(accF[mf][nf], accC[mf][nf], h * 2 + 1);
                __half h0 = __float2half_rn(v0);
                __half h1 = __float2half_rn(v1);
                __half l0 = __float2half_rn(v0 - __half2float(h0));
                __half l1 = __float2half_rn(v1 - __half2float(h1));
                *(__half2*)(Ch + (size_t)r * DD + c0) = __half2(h0, h1);
                *(__half2*)(Cl + (size_t)r * DD + c0) = __half2(l0, l1);
            }
        }
}

// Vd projection (single-term core): output rounded to f16 anyway.
__global__ void __launch_bounds__(128, 4)
mma_gemm_vd(const __half* __restrict__ Xh, const __half* __restrict__ Bvh,
            __half* __restrict__ Vh)
{
    const int m0 = blockIdx.y * 128;
    const int n0 = blockIdx.x * 64;

    extern __shared__ char sm[];
    float accF[4][4][4] = {};
    gemm_core_f16_1(Xh, Bvh, m0, n0, EE, EE, EE >> 5, sm, accF);

    const int lane = threadIdx.x & 31;
    const int wid = threadIdx.x >> 5;
    const int wm = wid >> 1, wn = wid & 1;
    const int g = lane >> 2, t2 = (lane & 3) * 2;
#pragma unroll
    for (int mf = 0; mf < 4; mf++)
#pragma unroll
        for (int nf = 0; nf < 4; nf++) {
            const int r0 = m0 + wm * 64 + mf * 16 + g;
            const int c0 = n0 + wn * 32 + nf * 8 + t2;
#pragma unroll
            for (int h = 0; h < 2; h++) {
                const int r = r0 + h * 8;
                Vh[(size_t)c0 * (BB * NN) + r] =
                    __float2half_rn(accF[mf][nf][h * 2 + 0]);
                Vh[(size_t)(c0 + 1) * (BB * NN) + r] =
                    __float2half_rn(accF[mf][nf][h * 2 + 1]);
            }
        }
}

// S GEMM (split-3 core) with fused quirk + __expf + row-sum epilogue.
__global__ void __launch_bounds__(128, 3)
mma_gemm_sexp(const __half* __restrict__ Qh, const __half* __restrict__ Ql,
              const __half* __restrict__ Kh, const __half* __restrict__ Kl,
              __half* __restrict__ Ph, float* __restrict__ rsum)
{
    const int m0 = blockIdx.y * 128;
    const int n0 = blockIdx.x * 64;
    if (n0 > m0 + 127) return;          // fully masked tile
    const int z = blockIdx.z;

    const __half* Ah = Qh + (size_t)z * NN * DD;
    const __half* Al = Ql + (size_t)z * NN * DD;
    const __half* Bh = Kh + (size_t)z * NN * DD;
    const __half* Bl = Kl + (size_t)z * NN * DD;
    Ph += (size_t)z * NN * NN;
    rsum += (size_t)z * NN;

    extern __shared__ char sm[];
    float accF[4][4][4] = {};
    uint32_t accC[4][4][2] = {};
    gemm_core_f16(Ah, Al, Bh, Bl, m0, n0, DD, DD, DD >> 5, sm, accF, accC);

    const int lane = threadIdx.x & 31;
    const int wid = threadIdx.x >> 5;
    const int wm = wid >> 1, wn = wid & 1;
    const int g = lane >> 2, t2 = (lane & 3) * 2;
    const float alpha = 1.0f / 16.0f;

#pragma unroll
    for (int mf = 0; mf < 4; mf++) {
#pragma unroll
        for (int h = 0; h < 2; h++) {
            const int row = m0 + wm * 64 + mf * 16 + g + h * 8;
            float rs = 0.0f;
#pragma unroll
            for (int nf = 0; nf < 4; nf++) {
                const int col = n0 + wn * 32 + nf * 8 + t2;
                float s0 = f16v(accF[mf][nf], accC[mf][nf], h * 2 + 0) * alpha;
                float s1 = f16v(accF[mf][nf], accC[mf][nf], h * 2 + 1) * alpha;
                float e0 = (col > row) ? 0.0f
                           : __expf((s0 != 0.0f) ? s0 : NEG_FILL);
                float e1 = (col + 1 > row) ? 0.0f
                           : __expf((s1 != 0.0f) ? s1 : NEG_FILL);
                rs += e0 + e1;
                __half h0 = __float2half_rn(e0 * PSCALE);
                __half h1 = __float2half_rn(e1 * PSCALE);
                *(__half2*)(Ph + (size_t)row * NN + col) = __half2(h0, h1);
            }
            rs += __shfl_xor_sync(0xffffffff, rs, 1);
            rs += __shfl_xor_sync(0xffffffff, rs, 2);
            if ((lane & 3) == 0) atomicAdd(&rsum[row], rs);
        }
    }
}

// T GEMM (single-term 128x128 core), split-K halves, big-K first.
__global__ void __launch_bounds__(128, 2)
mma_gemm_tsplit(const __half* __restrict__ Ph, const __half* __restrict__ Vh,
                float* __restrict__ Tp0, float* __restrict__ Tp1)
{
    const int by = gridDim.y - 1 - blockIdx.y;
    const int m0 = by * 128;
    const int n0 = blockIdx.x * 128;
    const int batch = blockIdx.z >> 1;
    const int half = blockIdx.z & 1;

    const int kEnd = m0 + 128;          // causal K limit (multiple of 128)
    const int kh = kEnd >> 1;
    const int ks = half ? kh : 0;
    const int ke = half ? kEnd : kh;

    const __half* Ah = Ph + (size_t)batch * NN * NN + ks;
    const __half* Bh = Vh + (size_t)batch * NN + ks;
    float* Tp = (half ? Tp1 : Tp0) + (size_t)batch * NN * DD;

    extern __shared__ char sm[];
    float accF[4][8][4] = {};
    gemm_core_f16_1w(Ah, Bh, m0, n0, NN, BB * NN, (ke - ks) >> 5, sm, accF);

    const int lane = threadIdx.x & 31;
    const int wid = threadIdx.x >> 5;
    const int wm = wid >> 1, wn = wid & 1;
    const int g = lane >> 2, t2 = (lane & 3) * 2;
#pragma unroll
    for (int mf = 0; mf < 4; mf++)
#pragma unroll
        for (int nf = 0; nf < 8; nf++) {
            const int r0 = m0 + wm * 64 + mf * 16 + g;
            const int c0 = n0 + wn * 64 + nf * 8 + t2;
#pragma unroll
            for (int h = 0; h < 2; h++) {
                const int r = r0 + h * 8;
                *(float2*)(Tp + (size_t)r * DD + c0) =
                    make_float2(accF[mf][nf][h * 2 + 0], accF[mf][nf][h * 2 + 1]);
            }
        }
}

// Combine T partials, undo PSCALE, normalize, emit f16 hi/lo.
__global__ void __launch_bounds__(256)
combine_T(const float* __restrict__ p0, const float* __restrict__ p1,
          const float* __restrict__ rsum,
          __half* __restrict__ Th, __half* __restrict__ Tl)
{
    int i = blockIdx.x * 256 + threadIdx.x;          // over (BB*NN*DD)/4
    float4 a = ((const float4*)p0)[i];
    float4 b = ((const float4*)p1)[i];
    const float inv = PSCALE_INV / rsum[i >> 6];     // row = (i*4)/DD
    float v0 = (a.x + b.x) * inv, v1 = (a.y + b.y) * inv;
    float v2 = (a.z + b.z) * inv, v3 = (a.w + b.w) * inv;
    __half h0 = __float2half_rn(v0), h1 = __float2half_rn(v1);
    __half h2 = __float2half_rn(v2), h3 = __float2half_rn(v3);
    __half l0 = __float2half_rn(v0 - __half2float(h0));
    __half l1 = __float2half_rn(v1 - __half2float(h1));
    __half l2 = __float2half_rn(v2 - __half2float(h2));
    __half l3 = __float2half_rn(v3 - __half2float(h3));
    ((__half2*)Th)[i * 2 + 0] = __half2(h0, h1);
    ((__half2*)Th)[i * 2 + 1] = __half2(h2, h3);
    ((__half2*)Tl)[i * 2 + 0] = __half2(l0, l1);
    ((__half2*)Tl)[i * 2 + 1] = __half2(l2, l3);
}

// out = T @ Wvu (split-3 core), f32 out
__global__ void __launch_bounds__(128, 3)
mma_gemm_out(const __half* __restrict__ Ah, const __half* __restrict__ Al,
             const __half* __restrict__ Bh, const __half* __restrict__ Bl,
             float* __restrict__ Cf)
{
    const int m0 = blockIdx.y * 128;
    const int n0 = blockIdx.x * 64;
    extern __shared__ char sm[];
    float accF[4][4][4] = {};
    uint32_t accC[4][4][2] = {};
    gemm_core_f16(Ah, Al, Bh, Bl, m0, n0, DD, DD, DD >> 5, sm, accF, accC);

    const int lane = threadIdx.x & 31;
    const int wid = threadIdx.x >> 5;
    const int wm = wid >> 1, wn = wid & 1;
    const int g = lane >> 2, t2 = (lane & 3) * 2;
#pragma unroll
    for (int mf = 0; mf < 4; mf++)
#pragma unroll
        for (int nf = 0; nf < 4; nf++) {
            const int r0 = m0 + wm * 64 + mf * 16 + g;
            const int c0 = n0 + wn * 32 + nf * 8 + t2;
#pragma unroll
            for (int h = 0; h < 2; h++) {
                const int r = r0 + h * 8;
                *(float2*)(Cf + (size_t)r * EE + c0) = make_float2(
                    f16v(accF[mf][nf], accC[mf][nf], h * 2 + 0),
                    f16v(accF[mf][nf], accC[mf][nf], h * 2 + 1));
            }
        }
}

// Merged prep kernel: X f16 split + 4 weight transpose/f16-splits + rsum zero.
__global__ void __launch_bounds__(256)
prep_all(const float* __restrict__ X,
         const float* __restrict__ Wq, const float* __restrict__ Wk,
         const float* __restrict__ Wvd, const float* __restrict__ Wvu,
         __half* __restrict__ Xh, __half* __restrict__ Xl,
         __half* __restrict__ WqTh, __half* __restrict__ WqTl,
         __half* __restrict__ WkTh, __half* __restrict__ WkTl,
         __half* __restrict__ WvdTh, __half* __restrict__ WvdTl,
         __half* __restrict__ WvuTh, __half* __restrict__ WvuTl,
         float* __restrict__ rsum)
{
    const int b = blockIdx.x;
    const int tid = threadIdx.x;

    if (b < 16384) {                       // ---- X split
        int i = b * 256 + tid;
        float4 v = ((const float4*)X)[i];
        __half h0 = __float2half_rn(v.x), h1 = __float2half_rn(v.y);
        __half h2 = __float2half_rn(v.z), h3 = __float2half_rn(v.w);
        __half l0 = __float2half_rn(v.x - __half2float(h0));
        __half l1 = __float2half_rn(v.y - __half2float(h1));
        __half l2 = __float2half_rn(v.z - __half2float(h2));
        __half l3 = __float2half_rn(v.w - __half2float(h3));
        ((__half2*)Xh)[i * 2 + 0] = __half2(h0, h1);
        ((__half2*)Xh)[i * 2 + 1] = __half2(h2, h3);
        ((__half2*)Xl)[i * 2 + 0] = __half2(l0, l1);
        ((__half2*)Xl)[i * 2 + 1] = __half2(l2, l3);
        return;
    }
    if (b < 16384 + 1024) {                // ---- weight transpose + f16 split
        const int t = b - 16384;
        const int w = t >> 8;
        const int s = t & 255;
        const float* src; __half *dh, *dl;
        int M, N, gx, gy;
        if (w < 3) {                       // [EE, DD] -> [DD, EE]
            M = EE; N = DD; gx = s & 7; gy = s >> 3;
            src = (w == 0) ? Wq : (w == 1) ? Wk : Wvd;
            dh = (w == 0) ? WqTh : (w == 1) ? WkTh : WvdTh;
            dl = (w == 0) ? WqTl : (w == 1) ? WkTl : WvdTl;
        } else {                           // [DD, EE] -> [EE, DD]
            M = DD; N = EE; gx = s & 31; gy = s >> 5;
            src = Wvu; dh = WvuTh; dl = WvuTl;
        }
        __shared__ float tb[32][33];
        const int bx = gx * 32, by = gy * 32;
        const int x = tid & 31, y = tid >> 5;
#pragma unroll
        for (int i = 0; i < 32; i += 8)
            tb[y + i][x] = src[(size_t)(by + y + i) * N + bx + x];
        __syncthreads();
#pragma unroll
        for (int i = 0; i < 32; i += 8) {
            float v = tb[x][y + i];
            __half h = __float2half_rn(v);
            dh[(size_t)(bx + y + i) * M + by + x] = h;
            dl[(size_t)(bx + y + i) * M + by + x] =
                __float2half_rn(v - __half2float(h));
        }
        return;
    }
    {                                      // ---- zero rsum
        const int t = b - (16384 + 1024);
        int i = t * 256 + tid;
        ((float4*)rsum)[i] = make_float4(0.f, 0.f, 0.f, 0.f);
    }
}

// ---------------------------------------------------------------------------
extern "C" void kernel_launch(void* const* d_in, const int* in_sizes, int n_in,
                              void* d_out, int out_size)
{
    (void)in_sizes; (void)n_in; (void)out_size;
    const float* X   = (const float*)d_in[0];
    const float* Wq  = (const float*)d_in[1];
    const float* Wk  = (const float*)d_in[2];
    const float* Wvd = (const float*)d_in[3];
    const float* Wvu = (const float*)d_in[4];
    float* out = (float*)d_out;

    __half *pXh, *pXl, *pQh, *pQl, *pKh, *pKl, *pTh, *pTl, *pVdTh, *pPh;
    __half *pWqTh, *pWqTl, *pWkTh, *pWkTl, *pWvdTh, *pWvdTl, *pWvuTh, *pWvuTl;
    float *pTp0, *pTp1, *pRs;
    cudaGetSymbolAddress((void**)&pXh, g_Xh);     cudaGetSymbolAddress((void**)&pXl, g_Xl);
    cudaGetSymbolAddress((void**)&pQh, g_Qh);     cudaGetSymbolAddress((void**)&pQl, g_Ql);
    cudaGetSymbolAddress((void**)&pKh, g_Kh);     cudaGetSymbolAddress((void**)&pKl, g_Kl);
    cudaGetSymbolAddress((void**)&pVdTh, g_VdTh);
    cudaGetSymbolAddress((void**)&pTh, g_Th);     cudaGetSymbolAddress((void**)&pTl, g_Tl);
    cudaGetSymbolAddress((void**)&pTp0, g_Tp0);   cudaGetSymbolAddress((void**)&pTp1, g_Tp1);
    cudaGetSymbolAddress((void**)&pRs, g_rsum);
    cudaGetSymbolAddress((void**)&pWqTh, g_WqTh); cudaGetSymbolAddress((void**)&pWqTl, g_WqTl);
    cudaGetSymbolAddress((void**)&pWkTh, g_WkTh); cudaGetSymbolAddress((void**)&pWkTl, g_WkTl);
    cudaGetSymbolAddress((void**)&pWvdTh, g_WvdTh); cudaGetSymbolAddress((void**)&pWvdTl, g_WvdTl);
    cudaGetSymbolAddress((void**)&pWvuTh, g_WvuTh); cudaGetSymbolAddress((void**)&pWvuTl, g_WvuTl);
    cudaGetSymbolAddress((void**)&pPh, g_Ph);

    cudaFuncSetAttribute(mma_gemm_qk,
                         cudaFuncAttributeMaxDynamicSharedMemorySize, F16_SMEM);
    cudaFuncSetAttribute(mma_gemm_vd,
                         cudaFuncAttributeMaxDynamicSharedMemorySize, T1_SMEM);
    cudaFuncSetAttribute(mma_gemm_sexp,
                         cudaFuncAttributeMaxDynamicSharedMemorySize, F16_SMEM);
    cudaFuncSetAttribute(mma_gemm_tsplit,
                         cudaFuncAttributeMaxDynamicSharedMemorySize, T2_SMEM);
    cudaFuncSetAttribute(mma_gemm_out,
                         cudaFuncAttributeMaxDynamicSharedMemorySize, F16_SMEM);

    const dim3 blk(128);
    const dim3 pblk(256);

    // 0) merged prep
    prep_all<<<16384 + 1024 + 16, pblk>>>(
        X, Wq, Wk, Wvd, Wvu, pXh, pXl,
        pWqTh, pWqTl, pWkTh, pWkTl, pWvdTh, pWvdTl, pWvuTh, pWvuTl, pRs);

    // 1a) Q/K projection (split-3 core)
    mma_gemm_qk<<<dim3(4, 128, 2), blk, F16_SMEM>>>(
        pXh, pXl, pWqTh, pWqTl, pWkTh, pWkTl, pQh, pQl, pKh, pKl);

    // 1b) VdT projection (single-term core)
    mma_gemm_vd<<<dim3(4, 128), blk, T1_SMEM>>>(pXh, pWvdTh, pVdTh);

    // 2) S = Q@K^T/16 with fused quirk+__expf+rowsum epilogue (split-3 core)
    mma_gemm_sexp<<<dim3(64, 32, BB), blk, F16_SMEM>>>(
        pQh, pQl, pKh, pKl, pPh, pRs);

    // 3) T partials = P' @ Vd (single-term 128x128 core), split-K, big-K first
    mma_gemm_tsplit<<<dim3(2, 32, BB * 2), blk, T2_SMEM>>>(
        pPh, pVdTh, pTp0, pTp1);

    // 4) combine + undo PSCALE + normalize -> Th/Tl (f16)
    combine_T<<<(BB * NN * DD / 4) / 256, pblk>>>(pTp0, pTp1, pRs, pTh, pTl);

    // 5) out = T @ Wvu (split-3 core)
    mma_gemm_out<<<dim3(16, 128, 1), blk, F16_SMEM>>>(
        pTh, pTl, pWvuTh, pWvuTl, out);
}